// round 17
// baseline (speedup 1.0000x reference)
#include <cuda_runtime.h>
#include <cuda_fp16.h>
#include <cstdint>

// ----------------------------------------------------------------------------
// MultiHeadAttn, pure fp16 tensor-core pipeline (K=512):
//   1) prep_kernel : x -> A1 fp16; Wq,Wv -> B1; Wup^T -> B2 (x 2^13)
//   2) gemm_mma<HALF_OUT=1> (128 thr, 128x128) : QVh = A1 @ B1^T   [512 CTAs]
//   3) band_attn v5 : cp.async fp16 tiles, windowed MMA attention
//   4) gemm_mma_64 (128 thr, 64x128 tile) : out = A2 @ B2^T  fp32  [512 CTAs]
//      (2 waves; avoids the single-wave CTA-spread tail that capped GEMM2)
// ----------------------------------------------------------------------------

#define M_ROWS   8192
#define N_SEQ    4096
#define NHEAD    8
#define CONTEXT  10
#define KDIM     512
#define NCHUNK   8           // 512 / 64

#define BSCALE   8192.0f     // 2^13
#define CSCALE   256.0f      // 2^8

__device__ __half g_A1[M_ROWS * KDIM];
__device__ __half g_A2[M_ROWS * KDIM];
__device__ __half g_B1[1024 * KDIM];
__device__ __half g_B2[512  * KDIM];
__device__ __half g_QVh[M_ROWS * 1024];

// ============================ PTX helpers ====================================
__device__ __forceinline__ uint32_t smem_u32(const void* p) {
    uint32_t a;
    asm("{ .reg .u64 t; cvta.to.shared.u64 t, %1; cvt.u32.u64 %0, t; }"
        : "=r"(a) : "l"(p));
    return a;
}
__device__ __forceinline__ void cp_async16(uint32_t dst, const void* src) {
    asm volatile("cp.async.cg.shared.global [%0], [%1], 16;"
                 :: "r"(dst), "l"(src) : "memory");
}
__device__ __forceinline__ void cp_async16_p(uint32_t dst, const void* src,
                                             uint32_t srcsz) {
    asm volatile("cp.async.cg.shared.global [%0], [%1], 16, %2;"
                 :: "r"(dst), "l"(src), "r"(srcsz) : "memory");
}
__device__ __forceinline__ void cp_commit() {
    asm volatile("cp.async.commit_group;" ::: "memory");
}
template <int N>
__device__ __forceinline__ void cp_wait() {
    asm volatile("cp.async.wait_group %0;" :: "n"(N) : "memory");
}
__device__ __forceinline__ void ldm_x4(uint32_t& r0, uint32_t& r1,
                                       uint32_t& r2, uint32_t& r3, uint32_t a) {
    asm volatile("ldmatrix.sync.aligned.m8n8.x4.shared.b16 {%0,%1,%2,%3}, [%4];"
                 : "=r"(r0), "=r"(r1), "=r"(r2), "=r"(r3) : "r"(a));
}
__device__ __forceinline__ void ldm_x4_t(uint32_t& r0, uint32_t& r1,
                                         uint32_t& r2, uint32_t& r3, uint32_t a) {
    asm volatile("ldmatrix.sync.aligned.m8n8.x4.trans.shared.b16 {%0,%1,%2,%3}, [%4];"
                 : "=r"(r0), "=r"(r1), "=r"(r2), "=r"(r3) : "r"(a));
}
__device__ __forceinline__ void mma16816(float* c, const uint32_t* a,
                                         const uint32_t* b) {
    asm volatile(
        "mma.sync.aligned.m16n8k16.row.col.f32.f16.f16.f32 "
        "{%0,%1,%2,%3}, {%4,%5,%6,%7}, {%8,%9}, {%0,%1,%2,%3};"
        : "+f"(c[0]), "+f"(c[1]), "+f"(c[2]), "+f"(c[3])
        : "r"(a[0]), "r"(a[1]), "r"(a[2]), "r"(a[3]), "r"(b[0]), "r"(b[1]));
}
__device__ __forceinline__ uint32_t h2u(__half2 v) {
    return *reinterpret_cast<uint32_t*>(&v);
}

// ===================== fused conversion / repack kernel ======================
__global__ void prep_kernel(const float* __restrict__ x,
                            const float* __restrict__ Wq,
                            const float* __restrict__ Wv,
                            const float* __restrict__ Wup,
                            __half* __restrict__ A1,
                            __half* __restrict__ B1,
                            __half* __restrict__ B2) {
    int bid = blockIdx.x;
    if (bid < 2048) {
        int idx = bid * 256 + threadIdx.x;          // [0, 8192*64)
        int row = idx >> 6;
        int kq  = (idx & 63) * 8;
        const float* src = x + (size_t)row * 512 + kq;
        float4 v0 = *(const float4*)src;
        float4 v1 = *(const float4*)(src + 4);
        __half2 h0 = __floats2half2_rn(v0.x, v0.y);
        __half2 h1 = __floats2half2_rn(v0.z, v0.w);
        __half2 h2 = __floats2half2_rn(v1.x, v1.y);
        __half2 h3 = __floats2half2_rn(v1.z, v1.w);
        *(uint4*)(A1 + (size_t)row * KDIM + kq) =
            make_uint4(h2u(h0), h2u(h1), h2u(h2), h2u(h3));
    } else {
        int idx = (bid - 2048) * 256 + threadIdx.x; // [0, 1024*512 + 512*512)
        if (idx < 1024 * 512) {
            int n = idx >> 9, d = idx & 511;
            float w;
            if (n < 512) {
                int hh = n >> 6, k2 = n & 63;
                w = Wq[hh * (512 * 64) + d * 64 + k2];
            } else {
                int nn = n - 512, hh = nn >> 6, k2 = nn & 63;
                w = Wv[hh * (512 * 64) + d * 64 + k2];
            }
            B1[n * KDIM + d] = __float2half_rn(w * BSCALE);
        } else {
            int i2 = idx - 1024 * 512;
            int n = i2 >> 9, d = i2 & 511;
            B2[n * KDIM + d] = __float2half_rn(Wup[d * 512 + n] * BSCALE);
        }
    }
}

// ============== GEMM variant A: 128 threads, 128x128 CTA tile ================
__device__ __forceinline__ void load_tiles(uint32_t sA, uint32_t sB,
                                           const __half* __restrict__ A,
                                           const __half* __restrict__ B,
                                           int bm, int bn, int ck, int tid) {
    const __half* Ab = A + (size_t)bm * KDIM + ck * 64;
    const __half* Bb = B + (size_t)bn * KDIM + ck * 64;
    #pragma unroll
    for (int g = 0; g < 8; g++) {
        int id  = g * 128 + tid;
        int row = id >> 3;
        int c16 = id & 7;
        uint32_t sw = row * 128 + ((c16 * 16) ^ ((row & 7) * 16));
        cp_async16(sA + sw, Ab + (size_t)row * KDIM + c16 * 8);
        cp_async16(sB + sw, Bb + (size_t)row * KDIM + c16 * 8);
    }
}

template <bool HALF_OUT>
__global__ __launch_bounds__(128)
void gemm_mma(const __half* __restrict__ A,
              const __half* __restrict__ B,
              void* __restrict__ Cv, int N, float escale) {
    extern __shared__ char smem[];
    uint32_t sb = smem_u32(smem);
    uint32_t SA[3] = {sb, sb + 32768, sb + 65536};
    uint32_t SB[3] = {sb + 16384, sb + 49152, sb + 81920};

    const int tid  = threadIdx.x;
    const int lane = tid & 31;
    const int warp = tid >> 5;
    const int wm   = (warp >> 1) * 64;
    const int wn   = (warp & 1) * 64;
    const int bm   = blockIdx.y * 128, bn = blockIdx.x * 128;

    const int fr = (lane & 7) + ((lane >> 3) & 1) * 8;
    const int fk = (lane >> 4) * 16;

    float acc[4][8][4];
    #pragma unroll
    for (int i = 0; i < 4; i++)
        #pragma unroll
        for (int j = 0; j < 8; j++)
            #pragma unroll
            for (int q = 0; q < 4; q++) acc[i][j][q] = 0.f;

    load_tiles(SA[0], SB[0], A, B, bm, bn, 0, tid); cp_commit();
    load_tiles(SA[1], SB[1], A, B, bm, bn, 1, tid); cp_commit();

    #pragma unroll 1
    for (int c = 0; c < NCHUNK; c++) {
        const int s = c % 3;
        uint32_t sA = SA[s], sBt = SB[s];

        if (c == NCHUNK - 1) cp_wait<0>(); else cp_wait<1>();
        __syncthreads();

        if (c + 2 < NCHUNK) {
            const int s2 = (c + 2) % 3;
            load_tiles(SA[s2], SB[s2], A, B, bm, bn, c + 2, tid);
            cp_commit();
        }

        #pragma unroll
        for (int ks = 0; ks < 4; ks++) {
            const int k0b = ks * 32;
            uint32_t af[4][4], bf[8][2];
            #pragma unroll
            for (int mi = 0; mi < 4; mi++) {
                int r = wm + mi * 16 + fr;
                uint32_t addr = sA + r * 128 + ((k0b + fk) ^ ((r & 7) * 16));
                ldm_x4(af[mi][0], af[mi][1], af[mi][2], af[mi][3], addr);
            }
            #pragma unroll
            for (int ni = 0; ni < 4; ni++) {
                int r = wn + ni * 16 + fr;
                uint32_t addr = sBt + r * 128 + ((k0b + fk) ^ ((r & 7) * 16));
                uint32_t r0, r1, r2, r3;
                ldm_x4(r0, r1, r2, r3, addr);
                bf[2 * ni][0]     = r0; bf[2 * ni][1]     = r2;
                bf[2 * ni + 1][0] = r1; bf[2 * ni + 1][1] = r3;
            }
            #pragma unroll
            for (int mi = 0; mi < 4; mi++)
                #pragma unroll
                for (int nj = 0; nj < 8; nj++)
                    mma16816(acc[mi][nj], af[mi], bf[nj]);
        }
    }

    const int er = lane >> 2;
    const int ec = (lane & 3) * 2;
    #pragma unroll
    for (int mi = 0; mi < 4; mi++) {
        #pragma unroll
        for (int nj = 0; nj < 8; nj++) {
            int row = bm + wm + mi * 16 + er;
            int col = bn + wn + nj * 8 + ec;
            if (HALF_OUT) {
                __half* Ch = (__half*)Cv;
                __half2 h0 = __floats2half2_rn(acc[mi][nj][0] * escale,
                                               acc[mi][nj][1] * escale);
                __half2 h1 = __floats2half2_rn(acc[mi][nj][2] * escale,
                                               acc[mi][nj][3] * escale);
                *(__half2*)(Ch + (size_t)row * N + col)       = h0;
                *(__half2*)(Ch + (size_t)(row + 8) * N + col) = h1;
            } else {
                float* C = (float*)Cv;
                *(float2*)(C + (size_t)row * N + col) =
                    make_float2(acc[mi][nj][0] * escale, acc[mi][nj][1] * escale);
                *(float2*)(C + (size_t)(row + 8) * N + col) =
                    make_float2(acc[mi][nj][2] * escale, acc[mi][nj][3] * escale);
            }
        }
    }
}

// ============ GEMM variant C: 128 threads, 64x128 CTA tile ===================
// 4 warps of 32x64 (2x2). Grid 4x128 = 512 CTAs -> 2 waves, spread amortized.
__device__ __forceinline__ void load_tiles64(uint32_t sA, uint32_t sB,
                                             const __half* __restrict__ A,
                                             const __half* __restrict__ B,
                                             int bm, int bn, int ck, int tid) {
    const __half* Ab = A + (size_t)bm * KDIM + ck * 64;
    const __half* Bb = B + (size_t)bn * KDIM + ck * 64;
    #pragma unroll
    for (int g = 0; g < 4; g++) {          // 64 rows x 8 = 512 granules
        int id  = g * 128 + tid;
        int row = id >> 3;
        int c16 = id & 7;
        uint32_t sw = row * 128 + ((c16 * 16) ^ ((row & 7) * 16));
        cp_async16(sA + sw, Ab + (size_t)row * KDIM + c16 * 8);
    }
    #pragma unroll
    for (int g = 0; g < 8; g++) {          // 128 rows x 8 = 1024 granules
        int id  = g * 128 + tid;
        int row = id >> 3;
        int c16 = id & 7;
        uint32_t sw = row * 128 + ((c16 * 16) ^ ((row & 7) * 16));
        cp_async16(sB + sw, Bb + (size_t)row * KDIM + c16 * 8);
    }
}

__global__ __launch_bounds__(128)
void gemm_mma_64(const __half* __restrict__ A,
                 const __half* __restrict__ B,
                 float* __restrict__ C, int N, float escale) {
    extern __shared__ char smem[];
    uint32_t sb = smem_u32(smem);
    // stage = A(8KB) + B(16KB) = 24KB; 3 stages = 72KB
    uint32_t SA[3] = {sb, sb + 24576, sb + 49152};
    uint32_t SB[3] = {sb + 8192, sb + 32768, sb + 57344};

    const int tid  = threadIdx.x;
    const int lane = tid & 31;
    const int warp = tid >> 5;
    const int wm   = (warp >> 1) * 32;   // 0 or 32
    const int wn   = (warp & 1) * 64;    // 0 or 64
    const int bm   = blockIdx.y * 64, bn = blockIdx.x * 128;

    const int fr = (lane & 7) + ((lane >> 3) & 1) * 8;
    const int fk = (lane >> 4) * 16;

    float acc[2][8][4];
    #pragma unroll
    for (int i = 0; i < 2; i++)
        #pragma unroll
        for (int j = 0; j < 8; j++)
            #pragma unroll
            for (int q = 0; q < 4; q++) acc[i][j][q] = 0.f;

    load_tiles64(SA[0], SB[0], A, B, bm, bn, 0, tid); cp_commit();
    load_tiles64(SA[1], SB[1], A, B, bm, bn, 1, tid); cp_commit();

    #pragma unroll 1
    for (int c = 0; c < NCHUNK; c++) {
        const int s = c % 3;
        uint32_t sA = SA[s], sBt = SB[s];

        if (c == NCHUNK - 1) cp_wait<0>(); else cp_wait<1>();
        __syncthreads();

        if (c + 2 < NCHUNK) {
            const int s2 = (c + 2) % 3;
            load_tiles64(SA[s2], SB[s2], A, B, bm, bn, c + 2, tid);
            cp_commit();
        }

        #pragma unroll
        for (int ks = 0; ks < 4; ks++) {
            const int k0b = ks * 32;
            uint32_t af[2][4], bf[8][2];
            #pragma unroll
            for (int mi = 0; mi < 2; mi++) {
                int r = wm + mi * 16 + fr;
                uint32_t addr = sA + r * 128 + ((k0b + fk) ^ ((r & 7) * 16));
                ldm_x4(af[mi][0], af[mi][1], af[mi][2], af[mi][3], addr);
            }
            #pragma unroll
            for (int ni = 0; ni < 4; ni++) {
                int r = wn + ni * 16 + fr;
                uint32_t addr = sBt + r * 128 + ((k0b + fk) ^ ((r & 7) * 16));
                uint32_t r0, r1, r2, r3;
                ldm_x4(r0, r1, r2, r3, addr);
                bf[2 * ni][0]     = r0; bf[2 * ni][1]     = r2;
                bf[2 * ni + 1][0] = r1; bf[2 * ni + 1][1] = r3;
            }
            #pragma unroll
            for (int mi = 0; mi < 2; mi++)
                #pragma unroll
                for (int nj = 0; nj < 8; nj++)
                    mma16816(acc[mi][nj], af[mi], bf[nj]);
        }
    }

    const int er = lane >> 2;
    const int ec = (lane & 3) * 2;
    #pragma unroll
    for (int mi = 0; mi < 2; mi++) {
        #pragma unroll
        for (int nj = 0; nj < 8; nj++) {
            int row = bm + wm + mi * 16 + er;
            int col = bn + wn + nj * 8 + ec;
            *(float2*)(C + (size_t)row * N + col) =
                make_float2(acc[mi][nj][0] * escale, acc[mi][nj][1] * escale);
            *(float2*)(C + (size_t)(row + 8) * N + col) =
                make_float2(acc[mi][nj][2] * escale, acc[mi][nj][3] * escale);
        }
    }
}

// ========================= band attention v5 (MMA) ===========================
#define TILE4   128
#define RB4     160
#define PP4     56          // P pitch in halves (112B rows)
#define SM_Q    0
#define SM_V    16384
#define SM_P    36864
#define SM_TOT  51200       // 16K Q/O + 20K V + 14K P

__global__ __launch_bounds__(256)
void band_attn_kernel(const __half* __restrict__ QVh,
                      __half* __restrict__ A2) {
    extern __shared__ char bsm[];
    const uint32_t sQ = smem_u32(bsm);
    const uint32_t sV = sQ + SM_V;
    const uint32_t sP = sQ + SM_P;
    __half* Ph = (__half*)(bsm + SM_P);

    const int bx   = blockIdx.x;          // [0, 512)
    const int tile = bx & 31;
    const int hd   = (bx >> 5) & 7;
    const int b    = bx >> 8;
    const int i0   = tile * TILE4;
    const int tid  = threadIdx.x;
    const int lane = tid & 31;
    const int rt   = tid >> 5;            // warp = row tile 0..7

    // ---- fill Q tile: swizzled cp.async from fp16 QVh ----
    for (int g = tid; g < TILE4 * 8; g += 256) {
        int r = g >> 3, c16 = g & 7;
        uint32_t sw = r * 128 + ((c16 * 16) ^ ((r & 7) * 16));
        cp_async16(sQ + sw,
                   QVh + (size_t)(b * N_SEQ + i0 + r) * 1024 + hd * 64 + c16 * 8);
    }
    // ---- fill V band rows (zero-fill halo via src-size=0) ----
    for (int g = tid; g < RB4 * 8; g += 256) {
        int r = g >> 3, c16 = g & 7;
        int j = i0 - CONTEXT + r;
        bool ok = (j >= 0) && (j < N_SEQ);
        const __half* src = QVh + (size_t)(b * N_SEQ + (ok ? j : 0)) * 1024
                                + 512 + hd * 64 + c16 * 8;
        uint32_t sw = r * 128 + ((c16 * 16) ^ ((r & 7) * 16));
        cp_async16_p(sV + sw, src, ok ? 16u : 0u);
    }
    cp_commit();
    cp_wait<0>();
    __syncthreads();

    const int fr = (lane & 7) + ((lane >> 3) & 1) * 8;
    const int fk = (lane >> 4) * 16;
    const int er = lane >> 2;
    const int ec = (lane & 3) * 2;
    const int rb = rt * 16;               // row/window base

    // ---- stage 1: S[16x48] = Q @ V^T over window ----
    float sacc[6][4];
    #pragma unroll
    for (int t = 0; t < 6; t++)
        #pragma unroll
        for (int q = 0; q < 4; q++) sacc[t][q] = 0.f;

    #pragma unroll
    for (int ks = 0; ks < 4; ks++) {
        const int k0b = ks * 32;
        uint32_t af[4], bf[6][2];
        int ar = rb + fr;
        ldm_x4(af[0], af[1], af[2], af[3],
               sQ + ar * 128 + ((k0b + fk) ^ ((ar & 7) * 16)));
        #pragma unroll
        for (int g = 0; g < 3; g++) {
            int vr = rb + g * 16 + fr;
            uint32_t r0, r1, r2, r3;
            ldm_x4(r0, r1, r2, r3,
                   sV + vr * 128 + ((k0b + fk) ^ ((vr & 7) * 16)));
            bf[2 * g][0]     = r0; bf[2 * g][1]     = r2;
            bf[2 * g + 1][0] = r1; bf[2 * g + 1][1] = r3;
        }
        #pragma unroll
        for (int t = 0; t < 6; t++)
            mma16816(sacc[t], af, bf[t]);
    }

    // ---- mask + exp -> P (local cols), rowsums in registers ----
    const float sscale = 1.0f / 16.0f;
    float slo = 0.f, shi = 0.f;
    #pragma unroll
    for (int t = 0; t < 6; t++) {
        int lc = t * 8 + ec;                    // local window col
        #pragma unroll
        for (int half = 0; half < 2; half++) {
            int rl = er + half * 8;             // row within warp tile
            float e0 = 0.f, e1 = 0.f;
            int d0 = lc - rl, d1 = d0 + 1;
            int j0 = i0 - CONTEXT + rb + lc;
            if (d0 >= 0 && d0 <= 2 * CONTEXT && d0 != CONTEXT &&
                j0 >= 0 && j0 < N_SEQ)
                e0 = __expf(sacc[t][2 * half] * sscale);
            if (d1 >= 0 && d1 <= 2 * CONTEXT && d1 != CONTEXT &&
                j0 + 1 >= 0 && j0 + 1 < N_SEQ)
                e1 = __expf(sacc[t][2 * half + 1] * sscale);
            *(__half2*)&Ph[(rb + rl) * PP4 + lc] = __floats2half2_rn(e0, e1);
            if (half == 0) slo += e0 + e1; else shi += e0 + e1;
        }
    }
    slo += __shfl_xor_sync(0xffffffffu, slo, 1);
    slo += __shfl_xor_sync(0xffffffffu, slo, 2);
    shi += __shfl_xor_sync(0xffffffffu, shi, 1);
    shi += __shfl_xor_sync(0xffffffffu, shi, 2);
    __syncwarp();          // this warp's P rows visible to its own ldmatrix

    // ---- stage 2: O[16x64] = P @ V (K = 48, B via trans ldmatrix) ----
    float oacc[8][4];
    #pragma unroll
    for (int t = 0; t < 8; t++)
        #pragma unroll
        for (int q = 0; q < 4; q++) oacc[t][q] = 0.f;

    #pragma unroll
    for (int ks = 0; ks < 3; ks++) {
        uint32_t af[4], bf[8][2];
        int ar = rb + fr;
        ldm_x4(af[0], af[1], af[2], af[3], sP + ar * 112 + ks * 32 + fk);
        #pragma unroll
        for (int g = 0; g < 4; g++) {
            int vr = rb + ks * 16 + fr;          // k index (band row)
            uint32_t nb = g * 32 + fk;           // n (dim) byte offset
            uint32_t r0, r1, r2, r3;
            ldm_x4_t(r0, r1, r2, r3,
                     sV + vr * 128 + (nb ^ ((vr & 7) * 16)));
            bf[2 * g][0]     = r0; bf[2 * g][1]     = r1;
            bf[2 * g + 1][0] = r2; bf[2 * g + 1][1] = r3;
        }
        #pragma unroll
        for (int t = 0; t < 8; t++)
            mma16816(oacc[t], af, bf[t]);
    }

    // ---- normalize, stage O into spent Q region (swizzled), coalesced STG --
    float inv0 = CSCALE / slo;
    float inv1 = CSCALE / shi;
    #pragma unroll
    for (int t = 0; t < 8; t++) {
        __half2 h0 = __floats2half2_rn(oacc[t][0] * inv0, oacc[t][1] * inv0);
        __half2 h1 = __floats2half2_rn(oacc[t][2] * inv1, oacc[t][3] * inv1);
        int r0 = rb + er, r1 = r0 + 8;
        uint32_t a0 = sQ + r0 * 128 + ((t * 16) ^ ((r0 & 7) * 16)) + 4 * (lane & 3);
        uint32_t a1 = sQ + r1 * 128 + ((t * 16) ^ ((r1 & 7) * 16)) + 4 * (lane & 3);
        *(__half2*)(bsm + (a0 - sQ) + SM_Q) = h0;
        *(__half2*)(bsm + (a1 - sQ) + SM_Q) = h1;
    }
    __syncthreads();

    // cooperative coalesced store: 128 rows x 128B
    for (int g = tid; g < TILE4 * 8; g += 256) {
        int row = g >> 3, q = g & 7;
        uint32_t off = row * 128 + ((q * 16) ^ ((row & 7) * 16));
        uint4 v = *(uint4*)(bsm + SM_Q + off);
        *(uint4*)(A2 + (size_t)(b * N_SEQ + i0 + row) * KDIM + hd * 64 + q * 8) = v;
    }
}

// ================================ launch =====================================
extern "C" void kernel_launch(void* const* d_in, const int* in_sizes, int n_in,
                              void* d_out, int out_size) {
    const float* x   = (const float*)d_in[0];
    const float* Wq  = (const float*)d_in[1];
    const float* Wv  = (const float*)d_in[2];
    const float* Wup = (const float*)d_in[3];

    __half *a1, *a2, *b1, *b2, *qvh;
    cudaGetSymbolAddress((void**)&a1,  g_A1);
    cudaGetSymbolAddress((void**)&a2,  g_A2);
    cudaGetSymbolAddress((void**)&b1,  g_B1);
    cudaGetSymbolAddress((void**)&b2,  g_B2);
    cudaGetSymbolAddress((void**)&qvh, g_QVh);

    const int SMEM_BYTES   = 98304;   // 3 stages x 32KB (gemm1)
    const int SMEM_BYTES64 = 73728;   // 3 stages x 24KB (gemm2)
    cudaFuncSetAttribute(gemm_mma<true>,
                         cudaFuncAttributeMaxDynamicSharedMemorySize, SMEM_BYTES);
    cudaFuncSetAttribute(gemm_mma_64,
                         cudaFuncAttributeMaxDynamicSharedMemorySize, SMEM_BYTES64);
    cudaFuncSetAttribute(band_attn_kernel,
                         cudaFuncAttributeMaxDynamicSharedMemorySize, SM_TOT);

    prep_kernel<<<2048 + 3072, 256>>>(x, Wq, Wv, Wup, a1, b1, b2);

    gemm_mma<true><<<dim3(1024 / 128, M_ROWS / 128), 128, SMEM_BYTES>>>(
        a1, b1, qvh, 1024, 1.0f / BSCALE);
    band_attn_kernel<<<2 * NHEAD * (N_SEQ / TILE4), 256, SM_TOT>>>(qvh, a2);
    gemm_mma_64<<<dim3(512 / 128, M_ROWS / 64), 128, SMEM_BYTES64>>>(
        a2, b2, (float*)d_out, 512, 1.0f / (BSCALE * CSCALE));
}